// round 2
// baseline (speedup 1.0000x reference)
#include <cuda_runtime.h>
#include <math.h>

// Shapes (fixed per problem): F: (2,3,128,128,128) = 12,582,912 ; I/S: (2,1,128,128,128) = 4,194,304
#define DIM   128
#define DIM2  (128*128)
#define VOL   (128*128*128)        // 2,097,152 per batch
#define NF    12582912             // F element count
#define NI    4194304              // I/S element count

#define TX 32
#define TY 8
#define TZ 32
#define NT 256

// LCC blocks: 4 x-tiles * 16 y-tiles * 4 z-chunks * 2 batches * 2 pairs = 1024
#define NLCC 1024
// Reduction blocks
#define NFRED 640
#define NSRED 192
#define NRED  (NFRED + 2*NSRED)   // 1024
#define NBLK  (NLCC + NRED)

// Accumulators (double):
// 0: sum (F0-F0g)^2
// 1,2,3: pair0 lcc: s_gp, s_gg, s_pp
// 4,5,6: pair1 lcc
// 7: sum S0*S0g   8: sum (S0+S0g)
// 9: sum S1*S1g  10: sum (S1+S1g)
__device__ double g_acc[12];

__global__ void zero_kernel() {
    if (threadIdx.x < 12) g_acc[threadIdx.x] = 0.0;
}

__device__ __forceinline__ double block_reduce(double v, double* sh) {
    #pragma unroll
    for (int o = 16; o > 0; o >>= 1) v += __shfl_down_sync(0xffffffffu, v, o);
    int lane = threadIdx.x & 31, wid = threadIdx.x >> 5;
    if (lane == 0) sh[wid] = v;
    __syncthreads();
    if (wid == 0) {
        v = (lane < (NT >> 5)) ? sh[lane] : 0.0;
        #pragma unroll
        for (int o = 4; o > 0; o >>= 1) v += __shfl_down_sync(0xffffffffu, v, o);
    }
    return v;  // valid on thread 0
}

__global__ __launch_bounds__(NT) void main_kernel(
    const float* __restrict__ F0,  const float* __restrict__ F0g,
    const float* __restrict__ I0,  const float* __restrict__ I0R,
    const float* __restrict__ I1,  const float* __restrict__ I1R,
    const float* __restrict__ S0,  const float* __restrict__ S0g,
    const float* __restrict__ S1,  const float* __restrict__ S1g)
{
    __shared__ float sg[12 * 36];
    __shared__ float sp[12 * 36];
    __shared__ float yg[8 * 36];
    __shared__ float yp[8 * 36];
    __shared__ double sh[8];

    int bid = blockIdx.x;

    if (bid < NLCC) {
        // ---------------- LCC (box-mean + demeaned dot products) ----------------
        int t = bid;
        int xt = t & 3;  t >>= 2;   // 4 x-tiles
        int yt = t & 15; t >>= 4;   // 16 y-tiles
        int zt = t & 3;  t >>= 2;   // 4 z-chunks
        int b  = t & 1;  t >>= 1;   // 2 batches
        int pair = t;               // 2 pairs

        const float* __restrict__ G = pair ? I1  : I0;
        const float* __restrict__ P = pair ? I1R : I0R;
        size_t base = (size_t)b * VOL;

        int x0 = xt * TX, y0 = yt * TY, z0 = zt * TZ;
        int tx = threadIdx.x & 31, ty = threadIdx.x >> 5;

        float rg[5] = {0,0,0,0,0}, rp[5] = {0,0,0,0,0};   // xy-sum z-rings
        float cg[5] = {0,0,0,0,0}, cp[5] = {0,0,0,0,0};   // center-value z-rings
        float a_gp = 0.f, a_gg = 0.f, a_pp = 0.f;

        for (int k = 0; k < TZ + 4; k++) {
            int z = z0 - 2 + k;
            bool zin = (z >= 0) & (z < DIM);
            __syncthreads();  // protect smem from prior-iter readers
            // stage halo slice (36 x 12) of both tensors
            for (int i = threadIdx.x; i < 12 * 36; i += NT) {
                int yy = i / 36, xx = i - yy * 36;
                int gy = y0 - 2 + yy, gx = x0 - 2 + xx;
                float vg = 0.f, vp = 0.f;
                if (zin && (unsigned)gy < DIM && (unsigned)gx < DIM) {
                    size_t off = base + (size_t)z * DIM2 + (size_t)gy * DIM + gx;
                    vg = G[off]; vp = P[off];
                }
                sg[i] = vg; sp[i] = vp;
            }
            __syncthreads();
            // 5-tap y reduction: yg[yo][x] = sum rows yo..yo+4
            for (int i = threadIdx.x; i < 8 * 36; i += NT) {
                int yo = i / 36, xx = i - yo * 36;
                float s1 = 0.f, s2 = 0.f;
                #pragma unroll
                for (int d = 0; d < 5; d++) {
                    s1 += sg[(yo + d) * 36 + xx];
                    s2 += sp[(yo + d) * 36 + xx];
                }
                yg[i] = s1; yp[i] = s2;
            }
            __syncthreads();
            // 5-tap x reduction -> new xy window sum for this thread's column
            float ng = 0.f, np = 0.f;
            #pragma unroll
            for (int d = 0; d < 5; d++) {
                ng += yg[ty * 36 + tx + d];
                np += yp[ty * 36 + tx + d];
            }
            float ncg = sg[(ty + 2) * 36 + tx + 2];
            float ncp = sp[(ty + 2) * 36 + tx + 2];
            // shift z-rings (fully unrolled -> stays in registers)
            #pragma unroll
            for (int j = 0; j < 4; j++) {
                rg[j] = rg[j + 1]; rp[j] = rp[j + 1];
                cg[j] = cg[j + 1]; cp[j] = cp[j + 1];
            }
            rg[4] = ng; rp[4] = np; cg[4] = ncg; cp[4] = ncp;
            if (k >= 4) {
                float mg = (rg[0] + rg[1] + rg[2] + rg[3] + rg[4]) * (1.f / 125.f);
                float mp = (rp[0] + rp[1] + rp[2] + rp[3] + rp[4]) * (1.f / 125.f);
                float dg = cg[2] - mg, dp = cp[2] - mp;
                a_gp += dg * dp; a_gg += dg * dg; a_pp += dp * dp;
            }
        }
        __syncthreads();
        double v;
        v = block_reduce((double)a_gp, sh);
        if (threadIdx.x == 0) atomicAdd(&g_acc[1 + 3 * pair], v);
        __syncthreads();
        v = block_reduce((double)a_gg, sh);
        if (threadIdx.x == 0) atomicAdd(&g_acc[2 + 3 * pair], v);
        __syncthreads();
        v = block_reduce((double)a_pp, sh);
        if (threadIdx.x == 0) atomicAdd(&g_acc[3 + 3 * pair], v);
    } else if (bid < NLCC + NFRED) {
        // ---------------- F reduction: sum (F0 - F0g)^2 ----------------
        int rb = bid - NLCC;
        const float4* __restrict__ A = (const float4*)F0;
        const float4* __restrict__ B = (const float4*)F0g;
        const int n4 = NF / 4;
        float acc = 0.f;
        for (int i = rb * NT + threadIdx.x; i < n4; i += NFRED * NT) {
            float4 a = A[i], b = B[i];
            float d0 = a.x - b.x, d1 = a.y - b.y, d2 = a.z - b.z, d3 = a.w - b.w;
            acc += d0 * d0 + d1 * d1 + d2 * d2 + d3 * d3;
        }
        double v = block_reduce((double)acc, sh);
        if (threadIdx.x == 0) atomicAdd(&g_acc[0], v);
    } else {
        // ---------------- Tversky reductions ----------------
        int rb = bid - NLCC - NFRED;
        int pair = rb >= NSRED;
        if (pair) rb -= NSRED;
        const float4* __restrict__ A = (const float4*)(pair ? S1  : S0);
        const float4* __restrict__ B = (const float4*)(pair ? S1g : S0g);
        const int n4 = NI / 4;
        float accp = 0.f, accs = 0.f;
        for (int i = rb * NT + threadIdx.x; i < n4; i += NSRED * NT) {
            float4 a = A[i], b = B[i];
            accp += a.x * b.x + a.y * b.y + a.z * b.z + a.w * b.w;
            accs += (a.x + b.x) + (a.y + b.y) + (a.z + b.z) + (a.w + b.w);
        }
        double v = block_reduce((double)accp, sh);
        if (threadIdx.x == 0) atomicAdd(&g_acc[7 + 2 * pair], v);
        __syncthreads();
        v = block_reduce((double)accs, sh);
        if (threadIdx.x == 0) atomicAdd(&g_acc[8 + 2 * pair], v);
    }
}

__global__ void finalize_kernel(float* out) {
    if (threadIdx.x == 0 && blockIdx.x == 0) {
        const double LAMBDA = 10.0, BETA = 10.0;
        const double omegaF = (double)NF;
        const double omegaI = (double)NI;

        double reg = sqrt(g_acc[0]) / omegaF;

        double lcc[2];
        #pragma unroll
        for (int p = 0; p < 2; p++) {
            double s_gp = g_acc[1 + 3 * p];
            double s_gg = g_acc[2 + 3 * p];
            double s_pp = g_acc[3 + 3 * p];
            double num = s_gp * s_gp;
            double den = s_gg * s_pp;
            den = den > 1e-5 ? den : 1e-5;
            lcc[p] = -(num / den) / omegaI;
        }

        double tv[2];
        #pragma unroll
        for (int p = 0; p < 2; p++) {
            double prod = g_acc[7 + 2 * p];
            double ssum = g_acc[8 + 2 * p];
            ssum = ssum > 1e-5 ? ssum : 1e-5;
            tv[p] = -prod / ssum;   // -0.5 * sum(2*g*p)/den
        }

        double total = reg + LAMBDA * (lcc[0] + lcc[1]) + BETA * (tv[0] + tv[1]);
        out[0] = (float)total;
    }
}

extern "C" void kernel_launch(void* const* d_in, const int* in_sizes, int n_in,
                              void* d_out, int out_size) {
    const float* F0  = (const float*)d_in[0];
    const float* F0g = (const float*)d_in[1];
    const float* I0  = (const float*)d_in[2];
    const float* I0R = (const float*)d_in[3];
    const float* I1  = (const float*)d_in[4];
    const float* I1R = (const float*)d_in[5];
    const float* S0  = (const float*)d_in[6];
    const float* S0g = (const float*)d_in[7];
    const float* S1  = (const float*)d_in[8];
    const float* S1g = (const float*)d_in[9];
    float* out = (float*)d_out;

    zero_kernel<<<1, 32>>>();
    main_kernel<<<NBLK, NT>>>(F0, F0g, I0, I0R, I1, I1R, S0, S0g, S1, S1g);
    finalize_kernel<<<1, 32>>>(out);
}

// round 4
// speedup vs baseline: 1.1698x; 1.1698x over previous
#include <cuda_runtime.h>
#include <math.h>

// Shapes: F: (2,3,128,128,128) = 12,582,912 ; I/S: (2,1,128,128,128) = 4,194,304
#define DIM   128
#define DIM2  (128*128)
#define VOL   (128*128*128)
#define NF    12582912
#define NI    4194304

#define TX 32
#define TY 8
#define TZ 32
#define NT 256

#define NLCC  1024     // 4 x * 16 y * 4 z * 2 batch * 2 pair
#define NFRED 640
#define NSRED 192
#define NRED  1024     // NFRED + 2*NSRED
#define NBLK  2048

// Accumulators (double), zero-initialized at module load, reset by finalizer:
// 0: sum (F0-F0g)^2
// 1,2,3: pair0 lcc s_gp, s_gg, s_pp ; 4,5,6: pair1
// 7: sum S0*S0g  8: sum (S0+S0g) ; 9,10: pair1
__device__ double g_acc[12];
__device__ unsigned int g_count;

__device__ __forceinline__ double block_reduce(double v, double* sh) {
    #pragma unroll
    for (int o = 16; o > 0; o >>= 1) v += __shfl_down_sync(0xffffffffu, v, o);
    int lane = threadIdx.x & 31, wid = threadIdx.x >> 5;
    if (lane == 0) sh[wid] = v;
    __syncthreads();
    if (wid == 0) {
        v = (lane < (NT >> 5)) ? sh[lane] : 0.0;
        #pragma unroll
        for (int o = 4; o > 0; o >>= 1) v += __shfl_down_sync(0xffffffffu, v, o);
    }
    return v;  // valid on thread 0
}

__global__ __launch_bounds__(NT) void main_kernel(
    const float* __restrict__ F0,  const float* __restrict__ F0g,
    const float* __restrict__ I0,  const float* __restrict__ I0R,
    const float* __restrict__ I1,  const float* __restrict__ I1R,
    const float* __restrict__ S0,  const float* __restrict__ S0g,
    const float* __restrict__ S1,  const float* __restrict__ S1g,
    float* __restrict__ out)
{
    __shared__ float sg[12 * 40];
    __shared__ float sp[12 * 40];
    __shared__ float yg[8 * 40];
    __shared__ float yp[8 * 40];
    __shared__ double sh[8];
    __shared__ unsigned int s_last;

    const int bid  = blockIdx.x;
    const int role = bid & 1;          // interleave LCC / reduction across waves
    const int sub  = bid >> 1;
    const int tid  = threadIdx.x;

    if (role == 0) {
        // ======================= LCC (box-mean + demeaned dots) =======================
        int t = sub;
        int xt = t & 3;  t >>= 2;
        int yt = t & 15; t >>= 4;
        int zt = t & 3;  t >>= 2;
        int b  = t & 1;  t >>= 1;
        int pair = t;

        const float* __restrict__ G = pair ? I1  : I0;
        const float* __restrict__ P = pair ? I1R : I0R;
        const size_t base = (size_t)b * VOL;

        const int x0 = xt * TX, y0 = yt * TY, z0 = zt * TZ;
        const int tx = tid & 31, ty = tid >> 5;

        // ---- loop-invariant staging job: 240 float4 jobs (120 per tensor) ----
        const bool stager = tid < 240;
        const int  jj = (tid < 120) ? tid : tid - 120;     // 0..119
        const int  yy = jj / 10, xs = jj - yy * 10;
        const int  gy = y0 - 2 + yy;
        const int  gx = x0 - 4 + xs * 4;                   // aligned float4, fully in or out
        const bool xyok = stager && ((unsigned)gy < DIM) && ((unsigned)gx < DIM);
        const float* __restrict__ srcT = (tid < 120) ? G : P;
        float* dstT = (tid < 120) ? sg : sp;
        const int  soff = yy * 40 + xs * 4;
        const size_t goff = base + (size_t)gy * DIM + gx;

        // ---- loop-invariant y-pass jobs: 576 jobs (288 per tensor), <=3 per thread ----
        int   yoffA[3];          // in/out base offset yo*40+xx
        const float* ysrc[3];
        float* ydst[3];
        int nyjobs = 0;
        #pragma unroll
        for (int q = 0; q < 3; q++) {
            int i = tid + q * NT;
            if (i < 576) {
                int ii = (i < 288) ? i : i - 288;
                int yo = ii / 36, xx = ii - yo * 36 + 2;   // xx in 2..37
                yoffA[nyjobs] = yo * 40 + xx;
                ysrc[nyjobs]  = (i < 288) ? sg : sp;
                ydst[nyjobs]  = (i < 288) ? yg : yp;
                nyjobs++;
            }
        }

        // preload slice k=0 (z = z0-2)
        float4 pf = make_float4(0.f, 0.f, 0.f, 0.f);
        {
            int z = z0 - 2;
            if (xyok && z >= 0)
                pf = *(const float4*)(srcT + goff + (size_t)z * DIM2);
        }

        float rg[5] = {0,0,0,0,0}, rp[5] = {0,0,0,0,0};
        float cg[5] = {0,0,0,0,0}, cp[5] = {0,0,0,0,0};
        float a_gp = 0.f, a_gg = 0.f, a_pp = 0.f;

        for (int k = 0; k < TZ + 4; k++) {
            __syncthreads();                    // prior readers done
            if (stager) *(float4*)(dstT + soff) = pf;
            __syncthreads();

            // prefetch next slice (latency overlapped with y/x passes below)
            float4 nx = make_float4(0.f, 0.f, 0.f, 0.f);
            {
                int zn = z0 - 1 + k;
                if (k < TZ + 3 && xyok && (unsigned)zn < DIM)
                    nx = *(const float4*)(srcT + goff + (size_t)zn * DIM2);
            }

            // 5-tap y reduction
            #pragma unroll
            for (int q = 0; q < 3; q++) {
                if (q < nyjobs) {
                    const float* s = ysrc[q];
                    int o = yoffA[q];
                    float sum = s[o] + s[o + 40] + s[o + 80] + s[o + 120] + s[o + 160];
                    ydst[q][o] = sum;
                }
            }
            __syncthreads();

            // 5-tap x reduction -> this thread's xy window sum
            float ng = 0.f, np = 0.f;
            #pragma unroll
            for (int d = 0; d < 5; d++) {
                ng += yg[ty * 40 + tx + 2 + d];
                np += yp[ty * 40 + tx + 2 + d];
            }
            float ncg = sg[(ty + 2) * 40 + tx + 4];
            float ncp = sp[(ty + 2) * 40 + tx + 4];

            #pragma unroll
            for (int j = 0; j < 4; j++) {
                rg[j] = rg[j + 1]; rp[j] = rp[j + 1];
                cg[j] = cg[j + 1]; cp[j] = cp[j + 1];
            }
            rg[4] = ng; rp[4] = np; cg[4] = ncg; cp[4] = ncp;

            if (k >= 4) {
                float mg = (rg[0] + rg[1] + rg[2] + rg[3] + rg[4]) * (1.f / 125.f);
                float mp = (rp[0] + rp[1] + rp[2] + rp[3] + rp[4]) * (1.f / 125.f);
                float dg = cg[2] - mg, dp = cp[2] - mp;
                a_gp += dg * dp; a_gg += dg * dg; a_pp += dp * dp;
            }
            pf = nx;
        }
        __syncthreads();
        double v;
        v = block_reduce((double)a_gp, sh);
        if (tid == 0) atomicAdd(&g_acc[1 + 3 * pair], v);
        __syncthreads();
        v = block_reduce((double)a_gg, sh);
        if (tid == 0) atomicAdd(&g_acc[2 + 3 * pair], v);
        __syncthreads();
        v = block_reduce((double)a_pp, sh);
        if (tid == 0) atomicAdd(&g_acc[3 + 3 * pair], v);
    } else if (sub < NFRED) {
        // ======================= F reduction: sum (F0-F0g)^2 =======================
        const float4* __restrict__ A = (const float4*)F0;
        const float4* __restrict__ B = (const float4*)F0g;
        const int n4 = NF / 4;
        float acc = 0.f;
        for (int i = sub * NT + tid; i < n4; i += NFRED * NT) {
            float4 a = __ldcs(A + i), b = __ldcs(B + i);
            float d0 = a.x - b.x, d1 = a.y - b.y, d2 = a.z - b.z, d3 = a.w - b.w;
            acc += d0 * d0 + d1 * d1 + d2 * d2 + d3 * d3;
        }
        double v = block_reduce((double)acc, sh);
        if (tid == 0) atomicAdd(&g_acc[0], v);
    } else {
        // ======================= Tversky reductions =======================
        int rb = sub - NFRED;
        int pair = rb >= NSRED;
        if (pair) rb -= NSRED;
        const float4* __restrict__ A = (const float4*)(pair ? S1  : S0);
        const float4* __restrict__ B = (const float4*)(pair ? S1g : S0g);
        const int n4 = NI / 4;
        float accp = 0.f, accs = 0.f;
        for (int i = rb * NT + tid; i < n4; i += NSRED * NT) {
            float4 a = __ldcs(A + i), b = __ldcs(B + i);
            accp += a.x * b.x + a.y * b.y + a.z * b.z + a.w * b.w;
            accs += (a.x + b.x) + (a.y + b.y) + (a.z + b.z) + (a.w + b.w);
        }
        double v = block_reduce((double)accp, sh);
        if (tid == 0) atomicAdd(&g_acc[7 + 2 * pair], v);
        __syncthreads();
        v = block_reduce((double)accs, sh);
        if (tid == 0) atomicAdd(&g_acc[8 + 2 * pair], v);
    }

    // ======================= last-block finalize =======================
    if (tid == 0) {
        __threadfence();
        unsigned int old = atomicAdd(&g_count, 1u);
        s_last = (old == NBLK - 1) ? 1u : 0u;
    }
    __syncthreads();
    if (s_last && tid == 0) {
        __threadfence();
        const double LAMBDA = 10.0, BETA = 10.0;
        volatile double* acc = g_acc;

        double reg = sqrt(acc[0]) / (double)NF;

        double lcc_sum = 0.0;
        #pragma unroll
        for (int p = 0; p < 2; p++) {
            double s_gp = acc[1 + 3 * p];
            double s_gg = acc[2 + 3 * p];
            double s_pp = acc[3 + 3 * p];
            double den = s_gg * s_pp;
            den = den > 1e-5 ? den : 1e-5;
            lcc_sum += -(s_gp * s_gp / den) / (double)NI;
        }

        double tv_sum = 0.0;
        #pragma unroll
        for (int p = 0; p < 2; p++) {
            double prod = acc[7 + 2 * p];
            double ssum = acc[8 + 2 * p];
            ssum = ssum > 1e-5 ? ssum : 1e-5;
            tv_sum += -prod / ssum;
        }

        out[0] = (float)(reg + LAMBDA * lcc_sum + BETA * tv_sum);

        // reset state for next (graph-replayed) run
        #pragma unroll
        for (int i = 0; i < 12; i++) g_acc[i] = 0.0;
        __threadfence();
        g_count = 0u;
    }
}

extern "C" void kernel_launch(void* const* d_in, const int* in_sizes, int n_in,
                              void* d_out, int out_size) {
    const float* F0  = (const float*)d_in[0];
    const float* F0g = (const float*)d_in[1];
    const float* I0  = (const float*)d_in[2];
    const float* I0R = (const float*)d_in[3];
    const float* I1  = (const float*)d_in[4];
    const float* I1R = (const float*)d_in[5];
    const float* S0  = (const float*)d_in[6];
    const float* S0g = (const float*)d_in[7];
    const float* S1  = (const float*)d_in[8];
    const float* S1g = (const float*)d_in[9];
    float* out = (float*)d_out;

    main_kernel<<<NBLK, NT>>>(F0, F0g, I0, I0R, I1, I1R, S0, S0g, S1, S1g, out);
}

// round 5
// speedup vs baseline: 1.2684x; 1.0843x over previous
#include <cuda_runtime.h>
#include <math.h>

// Shapes: F: (2,3,128,128,128) = 12,582,912 ; I/S: (2,1,128,128,128) = 4,194,304
#define DIM   128
#define DIM2  (128*128)
#define VOL   (128*128*128)
#define NF    12582912
#define NI    4194304

#define TX 32
#define TY 8
#define TZ 32
#define NT 256
#define NSLICE 36                   // TZ + 4

#define NLCC  1024     // 4 x * 16 y * 4 z * 2 batch * 2 pair
#define NFRED 640
#define NSRED 192
#define NBLK  2048

// Accumulators (double), zero-init at load, reset by finalizer each run:
// 0: sum (F0-F0g)^2 ; 1..3 pair0 lcc s_gp,s_gg,s_pp ; 4..6 pair1
// 7: sum S0*S0g 8: sum(S0+S0g) ; 9,10: pair1
__device__ double g_acc[12];
__device__ unsigned int g_count;

__device__ __forceinline__ double block_reduce(double v, double* sh) {
    #pragma unroll
    for (int o = 16; o > 0; o >>= 1) v += __shfl_down_sync(0xffffffffu, v, o);
    int lane = threadIdx.x & 31, wid = threadIdx.x >> 5;
    if (lane == 0) sh[wid] = v;
    __syncthreads();
    if (wid == 0) {
        v = (lane < (NT >> 5)) ? sh[lane] : 0.0;
        #pragma unroll
        for (int o = 4; o > 0; o >>= 1) v += __shfl_down_sync(0xffffffffu, v, o);
    }
    return v;  // valid on thread 0
}

__global__ __launch_bounds__(NT, 5) void main_kernel(
    const float* __restrict__ F0,  const float* __restrict__ F0g,
    const float* __restrict__ I0,  const float* __restrict__ I0R,
    const float* __restrict__ I1,  const float* __restrict__ I1R,
    const float* __restrict__ S0,  const float* __restrict__ S0g,
    const float* __restrict__ S1,  const float* __restrict__ S1g,
    float* __restrict__ out)
{
    __shared__ float sg3[3][12 * 40];
    __shared__ float sp3[3][12 * 40];
    __shared__ float yg2[2][8 * 40];
    __shared__ float yp2[2][8 * 40];
    __shared__ double sh[8];
    __shared__ unsigned int s_last;

    const int bid  = blockIdx.x;
    const int role = bid & 1;        // interleave LCC / reduction across waves
    const int sub  = bid >> 1;
    const int tid  = threadIdx.x;

    if (role == 0) {
        // ================= LCC: on-the-fly 5x5x5 box-mean + demeaned dots =================
        int t = sub;
        int xt = t & 3;  t >>= 2;
        int yt = t & 15; t >>= 4;
        int zt = t & 3;  t >>= 2;
        int b  = t & 1;  t >>= 1;
        int pair = t;

        const float* __restrict__ G = pair ? I1  : I0;
        const float* __restrict__ P = pair ? I1R : I0R;
        const size_t base = (size_t)b * VOL;

        const int x0 = xt * TX, y0 = yt * TY, z0 = zt * TZ;
        const int tx = tid & 31, ty = tid >> 5;

        // ---- static staging job: 240 float4 jobs (120 per tensor) ----
        const bool stager = tid < 240;
        const bool isG_st = tid < 120;
        const int  jj = isG_st ? tid : tid - 120;          // 0..119
        const int  yy = jj / 10, xs = jj - yy * 10;
        const int  gy = y0 - 2 + yy;
        const int  gx = x0 - 4 + xs * 4;                   // aligned float4: fully in or out
        const bool xyok = stager && ((unsigned)gy < DIM) && ((unsigned)gx < DIM);
        const float* __restrict__ srcT = isG_st ? G : P;
        const int   soff = yy * 40 + xs * 4;
        const size_t goff = base + (size_t)gy * DIM + gx;

        // ---- static y-pass jobs (576 total: 288 G then 288 P) ----
        // q=0: i=tid      (<288 always G)        ii = tid
        // q=1: i=tid+256  G if tid<32 else P     ii = tid<32 ? tid+256 : tid-32
        // q=2: i=tid+512  valid if tid<64, P     ii = tid+224
        const int  ii0 = tid;
        const int  yo0 = ii0 / 36, yoff0 = yo0 * 40 + (ii0 - yo0 * 36) + 2;
        const bool j1G = tid < 32;
        const int  ii1 = j1G ? tid + 256 : tid - 32;
        const int  yo1 = ii1 / 36, yoff1 = yo1 * 40 + (ii1 - yo1 * 36) + 2;
        const bool j2v = tid < 64;
        const int  ii2 = tid + 224;
        const int  yo2 = ii2 / 36, yoff2 = yo2 * 40 + (ii2 - yo2 * 36) + 2;

        // preload + stage slice 0 (z = z0-2) into buffer 0
        float4 pf = make_float4(0.f, 0.f, 0.f, 0.f);
        if (xyok && z0 - 2 >= 0)
            pf = *(const float4*)(srcT + goff + (size_t)(z0 - 2) * DIM2);
        if (stager) {
            float* sb = isG_st ? sg3[0] : sp3[0];
            *(float4*)(sb + soff) = pf;
        }
        // prefetch slice 1
        pf = make_float4(0.f, 0.f, 0.f, 0.f);
        if (xyok && (unsigned)(z0 - 1) < DIM)
            pf = *(const float4*)(srcT + goff + (size_t)(z0 - 1) * DIM2);
        __syncthreads();

        float rg[5] = {0,0,0,0,0}, rp[5] = {0,0,0,0,0};   // xy-sum z-rings
        float cg1 = 0.f, cg2 = 0.f, cp1 = 0.f, cp2 = 0.f; // center 2-delay
        float a_gp = 0.f, a_gg = 0.f, a_pp = 0.f;

        int bcur = 0, bnext = 1, ybsel = 0;
        for (int k = 0; k < NSLICE; k++) {
            // (a) stage slice k+1 from prefetch reg; issue prefetch for slice k+2
            if (k + 1 < NSLICE && stager) {
                float* sb = isG_st ? sg3[bnext] : sp3[bnext];
                *(float4*)(sb + soff) = pf;
            }
            float4 nx = make_float4(0.f, 0.f, 0.f, 0.f);
            {
                int zn = z0 + k;                           // z of slice k+2
                if (k + 2 < NSLICE && xyok && (unsigned)zn < DIM)
                    nx = *(const float4*)(srcT + goff + (size_t)zn * DIM2);
            }

            // (b) 5-tap y reduction on sbuf[bcur] -> ybuf[ybsel]
            {
                const float* sG = sg3[bcur];
                const float* sP = sp3[bcur];
                float* yG = yg2[ybsel];
                float* yP = yp2[ybsel];
                {   // job 0: always G
                    int o = yoff0;
                    yG[o] = sG[o] + sG[o + 40] + sG[o + 80] + sG[o + 120] + sG[o + 160];
                }
                {   // job 1: G or P
                    int o = yoff1;
                    const float* s = j1G ? sG : sP;
                    float* d = j1G ? yG : yP;
                    d[o] = s[o] + s[o + 40] + s[o + 80] + s[o + 120] + s[o + 160];
                }
                if (j2v) {  // job 2: P
                    int o = yoff2;
                    yP[o] = sP[o] + sP[o + 40] + sP[o + 80] + sP[o + 120] + sP[o + 160];
                }
            }
            __syncthreads();   // the only barrier per slice

            // (d) 5-tap x reduction + ring update + accumulate
            {
                const float* yG = yg2[ybsel];
                const float* yP = yp2[ybsel];
                float ng = 0.f, np = 0.f;
                #pragma unroll
                for (int d = 0; d < 5; d++) {
                    ng += yG[ty * 40 + tx + 2 + d];
                    np += yP[ty * 40 + tx + 2 + d];
                }
                float ncg = sg3[bcur][(ty + 2) * 40 + tx + 4];
                float ncp = sp3[bcur][(ty + 2) * 40 + tx + 4];

                #pragma unroll
                for (int j = 0; j < 4; j++) { rg[j] = rg[j + 1]; rp[j] = rp[j + 1]; }
                rg[4] = ng; rp[4] = np;

                if (k >= 4) {
                    float mg = (rg[0] + rg[1] + rg[2] + rg[3] + rg[4]) * (1.f / 125.f);
                    float mp = (rp[0] + rp[1] + rp[2] + rp[3] + rp[4]) * (1.f / 125.f);
                    float dg = cg2 - mg, dp = cp2 - mp;   // centers from slice k-2
                    a_gp += dg * dp; a_gg += dg * dg; a_pp += dp * dp;
                }
                cg2 = cg1; cg1 = ncg;
                cp2 = cp1; cp1 = ncp;
            }

            pf = nx;
            bcur = bnext; bnext = bnext + 1; if (bnext == 3) bnext = 0;
            ybsel ^= 1;
        }
        __syncthreads();
        double v;
        v = block_reduce((double)a_gp, sh);
        if (tid == 0) atomicAdd(&g_acc[1 + 3 * pair], v);
        __syncthreads();
        v = block_reduce((double)a_gg, sh);
        if (tid == 0) atomicAdd(&g_acc[2 + 3 * pair], v);
        __syncthreads();
        v = block_reduce((double)a_pp, sh);
        if (tid == 0) atomicAdd(&g_acc[3 + 3 * pair], v);
    } else if (sub < NFRED) {
        // ================= F reduction: sum (F0-F0g)^2 =================
        const float4* __restrict__ A = (const float4*)F0;
        const float4* __restrict__ B = (const float4*)F0g;
        const int n4 = NF / 4;
        float acc = 0.f;
        for (int i = sub * NT + tid; i < n4; i += NFRED * NT) {
            float4 a = __ldcs(A + i), b = __ldcs(B + i);
            float d0 = a.x - b.x, d1 = a.y - b.y, d2 = a.z - b.z, d3 = a.w - b.w;
            acc += d0 * d0 + d1 * d1 + d2 * d2 + d3 * d3;
        }
        double v = block_reduce((double)acc, sh);
        if (tid == 0) atomicAdd(&g_acc[0], v);
    } else {
        // ================= Tversky reductions =================
        int rb = sub - NFRED;
        int pair = rb >= NSRED;
        if (pair) rb -= NSRED;
        const float4* __restrict__ A = (const float4*)(pair ? S1  : S0);
        const float4* __restrict__ B = (const float4*)(pair ? S1g : S0g);
        const int n4 = NI / 4;
        float accp = 0.f, accs = 0.f;
        for (int i = rb * NT + tid; i < n4; i += NSRED * NT) {
            float4 a = __ldcs(A + i), b = __ldcs(B + i);
            accp += a.x * b.x + a.y * b.y + a.z * b.z + a.w * b.w;
            accs += (a.x + b.x) + (a.y + b.y) + (a.z + b.z) + (a.w + b.w);
        }
        double v = block_reduce((double)accp, sh);
        if (tid == 0) atomicAdd(&g_acc[7 + 2 * pair], v);
        __syncthreads();
        v = block_reduce((double)accs, sh);
        if (tid == 0) atomicAdd(&g_acc[8 + 2 * pair], v);
    }

    // ================= last-block finalize =================
    if (tid == 0) {
        __threadfence();
        unsigned int old = atomicAdd(&g_count, 1u);
        s_last = (old == NBLK - 1) ? 1u : 0u;
    }
    __syncthreads();
    if (s_last && tid == 0) {
        __threadfence();
        const double LAMBDA = 10.0, BETA = 10.0;
        volatile double* acc = g_acc;

        double reg = sqrt(acc[0]) / (double)NF;

        double lcc_sum = 0.0;
        #pragma unroll
        for (int p = 0; p < 2; p++) {
            double s_gp = acc[1 + 3 * p];
            double s_gg = acc[2 + 3 * p];
            double s_pp = acc[3 + 3 * p];
            double den = s_gg * s_pp;
            den = den > 1e-5 ? den : 1e-5;
            lcc_sum += -(s_gp * s_gp / den) / (double)NI;
        }

        double tv_sum = 0.0;
        #pragma unroll
        for (int p = 0; p < 2; p++) {
            double prod = acc[7 + 2 * p];
            double ssum = acc[8 + 2 * p];
            ssum = ssum > 1e-5 ? ssum : 1e-5;
            tv_sum += -prod / ssum;
        }

        out[0] = (float)(reg + LAMBDA * lcc_sum + BETA * tv_sum);

        // reset state for next graph replay
        #pragma unroll
        for (int i = 0; i < 12; i++) g_acc[i] = 0.0;
        __threadfence();
        g_count = 0u;
    }
}

extern "C" void kernel_launch(void* const* d_in, const int* in_sizes, int n_in,
                              void* d_out, int out_size) {
    const float* F0  = (const float*)d_in[0];
    const float* F0g = (const float*)d_in[1];
    const float* I0  = (const float*)d_in[2];
    const float* I0R = (const float*)d_in[3];
    const float* I1  = (const float*)d_in[4];
    const float* I1R = (const float*)d_in[5];
    const float* S0  = (const float*)d_in[6];
    const float* S0g = (const float*)d_in[7];
    const float* S1  = (const float*)d_in[8];
    const float* S1g = (const float*)d_in[9];
    float* out = (float*)d_out;

    main_kernel<<<NBLK, NT>>>(F0, F0g, I0, I0R, I1, I1R, S0, S0g, S1, S1g, out);
}

// round 6
// speedup vs baseline: 1.3533x; 1.0670x over previous
#include <cuda_runtime.h>
#include <math.h>

// Shapes: F: (2,3,128,128,128) = 12,582,912 ; I/S: (2,1,128,128,128) = 4,194,304
#define DIM   128
#define DIM2  (128*128)
#define VOL   (128*128*128)
#define NF    12582912
#define NI    4194304

#define NT    384          // 12 warps

// LCC: 2 x-tiles(64) * 16 z-chunks(8) * 2 y-halves(64) * 2 batch * 2 pair = 256
#define NLCC  256
#define NFRED 320
#define NSRED 96
#define NBLK  768          // 256 LCC + 320 F + 192 S ; role = bid % 3

// Accumulators (double), zero-init at load, reset by finalizer each run:
// 0: sum (F0-F0g)^2 ; 1..3 pair0 lcc s_gp,s_gg,s_pp ; 4..6 pair1
// 7: sum S0*S0g 8: sum(S0+S0g) ; 9,10: pair1
__device__ double g_acc[12];
__device__ unsigned int g_count;

__device__ __forceinline__ double bred(double v, double* sh) {
    #pragma unroll
    for (int o = 16; o > 0; o >>= 1) v += __shfl_down_sync(0xffffffffu, v, o);
    int lane = threadIdx.x & 31, wid = threadIdx.x >> 5;
    if (lane == 0) sh[wid] = v;
    __syncthreads();
    if (wid == 0) {
        v = (lane < (NT >> 5)) ? sh[lane] : 0.0;
        #pragma unroll
        for (int o = 8; o > 0; o >>= 1) v += __shfl_down_sync(0xffffffffu, v, o);
    }
    return v;  // valid on thread 0
}

// 5-tap x-window sums for the 2 outputs this lane owns (x = 2*tx, 2*tx+1).
// v = own pair; h = halo pair (lane 0: x0-2,x0-1 ; lane 31: x0+64,x0+65).
__device__ __forceinline__ float2 xsum5(float2 v, float2 h, int tx) {
    float lmx = __shfl_up_sync(0xffffffffu, v.x, 1);
    float lmy = __shfl_up_sync(0xffffffffu, v.y, 1);
    float rpx = __shfl_down_sync(0xffffffffu, v.x, 1);
    float rpy = __shfl_down_sync(0xffffffffu, v.y, 1);
    if (tx == 0)  { lmx = h.x; lmy = h.y; }
    if (tx == 31) { rpx = h.x; rpy = h.y; }
    float m = lmy + v.x + v.y + rpx;
    return make_float2(lmx + m, m + rpy);
}

__global__ __launch_bounds__(NT, 2) void main_kernel(
    const float* __restrict__ F0,  const float* __restrict__ F0g,
    const float* __restrict__ I0,  const float* __restrict__ I0R,
    const float* __restrict__ I1,  const float* __restrict__ I1R,
    const float* __restrict__ S0,  const float* __restrict__ S0g,
    const float* __restrict__ S1,  const float* __restrict__ S1g,
    float* __restrict__ out)
{
    __shared__ float ybuf[2][12][128];   // [buf][plane][x-pair interleaved G,P] = 12 KB
    __shared__ double sh[12];
    __shared__ unsigned int s_last;

    const int bid = blockIdx.x;
    const int tid = threadIdx.x;
    const int r3  = bid % 3;

    if (r3 == 1) {
        // ============ LCC: y-loop / x-in-lanes(shuffle) / z-across-warps ============
        int sub = bid / 3;                 // 0..255
        int xt = sub & 1;  sub >>= 1;
        int zc = sub & 15; sub >>= 4;
        int yh = sub & 1;  sub >>= 1;
        int b  = sub & 1;  sub >>= 1;
        int pair = sub;

        const float* __restrict__ G = pair ? I1  : I0;
        const float* __restrict__ P = pair ? I1R : I0R;

        const int x0 = xt * 64, z0 = zc * 8, y0 = yh * 64;
        const int tx = tid & 31, w = tid >> 5;          // warp w owns plane z0-2+w
        const int z  = z0 - 2 + w;
        const bool zok = (unsigned)z < DIM;

        const size_t pbase = (size_t)b * VOL + (size_t)(zok ? z : 0) * DIM2
                             + (size_t)x0 + 2 * tx;
        const float* __restrict__ gp = G + pbase;
        const float* __restrict__ pp = P + pbase;

        const bool isL = (tx == 0), isR = (tx == 31);
        const bool haloAct = (isL && x0 > 0) || (isR && x0 + 64 < DIM);
        const int  hoff = isL ? -2 : 2;    // halo addr = main + hoff (lanes 0 / 31)

        const float2 zz = make_float2(0.f, 0.f);

        float2 vG, vP, hG, hP;
        // load row yload = y0-2
        {
            int gy = y0 - 2;
            bool yok = zok && ((unsigned)gy < DIM);
            vG = zz; vP = zz; hG = zz; hP = zz;
            if (yok) {
                size_t ro = (size_t)gy * DIM;
                vG = *(const float2*)(gp + ro);
                vP = *(const float2*)(pp + ro);
                if (haloAct) {
                    hG = *(const float2*)(gp + ro + hoff);
                    hP = *(const float2*)(pp + ro + hoff);
                }
            }
        }

        float2 rG[5] = {zz, zz, zz, zz, zz};
        float2 rP[5] = {zz, zz, zz, zz, zz};
        float2 cG1 = zz, cG2 = zz, cP1 = zz, cP2 = zz;
        float agp = 0.f, agg = 0.f, app = 0.f;
        const bool mainw = (w >= 2) && (w <= 9);
        int bufsel = 0;

        for (int k = 0; k < 68; k++) {
            // prefetch next row (yload_next = y0-1+k)
            float2 nG = zz, nP = zz, nhG = zz, nhP = zz;
            if (k < 67) {
                int gy = y0 - 1 + k;
                bool yok = zok && ((unsigned)gy < DIM);
                if (yok) {
                    size_t ro = (size_t)gy * DIM;
                    nG = *(const float2*)(gp + ro);
                    nP = *(const float2*)(pp + ro);
                    if (haloAct) {
                        nhG = *(const float2*)(gp + ro + hoff);
                        nhP = *(const float2*)(pp + ro + hoff);
                    }
                }
            }

            // x 5-tap via shuffles
            float2 xsG = xsum5(vG, hG, tx);
            float2 xsP = xsum5(vP, hP, tx);

            // y 5-tap via register ring (centered at yout = y0-4+k, valid k>=4)
            #pragma unroll
            for (int j = 0; j < 4; j++) { rG[j] = rG[j + 1]; rP[j] = rP[j + 1]; }
            rG[4] = xsG; rP[4] = xsP;
            float ysGx = rG[0].x + rG[1].x + rG[2].x + rG[3].x + rG[4].x;
            float ysGy = rG[0].y + rG[1].y + rG[2].y + rG[3].y + rG[4].y;
            float ysPx = rP[0].x + rP[1].x + rP[2].x + rP[3].x + rP[4].x;
            float ysPy = rP[0].y + rP[1].y + rP[2].y + rP[3].y + rP[4].y;

            // publish xy-sums: interleaved (G,P) per x → one STS.128
            *(float4*)&ybuf[bufsel][w][4 * tx] = make_float4(ysGx, ysPx, ysGy, ysPy);
            __syncthreads();     // the only barrier per y-step (double-buffered)

            // z 5-tap from SMEM + accumulate
            if (mainw && k >= 4) {
                float zgx = 0.f, zgy = 0.f, zpx = 0.f, zpy = 0.f;
                #pragma unroll
                for (int d = 0; d < 5; d++) {
                    float4 q = *(const float4*)&ybuf[bufsel][w - 2 + d][4 * tx];
                    zgx += q.x; zpx += q.y; zgy += q.z; zpy += q.w;
                }
                const float inv = 1.f / 125.f;
                float dgx = cG2.x - zgx * inv, dgy = cG2.y - zgy * inv;
                float dpx = cP2.x - zpx * inv, dpy = cP2.y - zpy * inv;
                agp += dgx * dpx + dgy * dpy;
                agg += dgx * dgx + dgy * dgy;
                app += dpx * dpx + dpy * dpy;
            }

            // slide pipelines
            cG2 = cG1; cG1 = vG; cP2 = cP1; cP1 = vP;
            vG = nG; vP = nP; hG = nhG; hP = nhP;
            bufsel ^= 1;
        }

        __syncthreads();
        double v;
        v = bred((double)agp, sh);
        if (tid == 0) atomicAdd(&g_acc[1 + 3 * pair], v);
        __syncthreads();
        v = bred((double)agg, sh);
        if (tid == 0) atomicAdd(&g_acc[2 + 3 * pair], v);
        __syncthreads();
        v = bred((double)app, sh);
        if (tid == 0) atomicAdd(&g_acc[3 + 3 * pair], v);
    } else {
        int rsub = (r3 == 0) ? (bid / 3) : (256 + bid / 3);   // 0..511
        if (rsub < NFRED) {
            // ============ F reduction: sum (F0-F0g)^2 ============
            const float4* __restrict__ A = (const float4*)F0;
            const float4* __restrict__ B = (const float4*)F0g;
            const int n4 = NF / 4;
            float acc = 0.f;
            for (int i = rsub * NT + tid; i < n4; i += NFRED * NT) {
                float4 a = __ldcs(A + i), bb = __ldcs(B + i);
                float d0 = a.x - bb.x, d1 = a.y - bb.y, d2 = a.z - bb.z, d3 = a.w - bb.w;
                acc += d0 * d0 + d1 * d1 + d2 * d2 + d3 * d3;
            }
            double v = bred((double)acc, sh);
            if (tid == 0) atomicAdd(&g_acc[0], v);
        } else {
            // ============ Tversky reductions ============
            int rb = rsub - NFRED;                 // 0..191
            int pair = rb >= NSRED;
            if (pair) rb -= NSRED;
            const float4* __restrict__ A = (const float4*)(pair ? S1  : S0);
            const float4* __restrict__ B = (const float4*)(pair ? S1g : S0g);
            const int n4 = NI / 4;
            float accp = 0.f, accs = 0.f;
            for (int i = rb * NT + tid; i < n4; i += NSRED * NT) {
                float4 a = __ldcs(A + i), bb = __ldcs(B + i);
                accp += a.x * bb.x + a.y * bb.y + a.z * bb.z + a.w * bb.w;
                accs += (a.x + bb.x) + (a.y + bb.y) + (a.z + bb.z) + (a.w + bb.w);
            }
            double v = bred((double)accp, sh);
            if (tid == 0) atomicAdd(&g_acc[7 + 2 * pair], v);
            __syncthreads();
            v = bred((double)accs, sh);
            if (tid == 0) atomicAdd(&g_acc[8 + 2 * pair], v);
        }
    }

    // ============ last-block finalize ============
    if (tid == 0) {
        __threadfence();
        unsigned int old = atomicAdd(&g_count, 1u);
        s_last = (old == NBLK - 1) ? 1u : 0u;
    }
    __syncthreads();
    if (s_last && tid == 0) {
        __threadfence();
        const double LAMBDA = 10.0, BETA = 10.0;
        volatile double* acc = g_acc;

        double reg = sqrt(acc[0]) / (double)NF;

        double lcc_sum = 0.0;
        #pragma unroll
        for (int p = 0; p < 2; p++) {
            double s_gp = acc[1 + 3 * p];
            double s_gg = acc[2 + 3 * p];
            double s_pp = acc[3 + 3 * p];
            double den = s_gg * s_pp;
            den = den > 1e-5 ? den : 1e-5;
            lcc_sum += -(s_gp * s_gp / den) / (double)NI;
        }

        double tv_sum = 0.0;
        #pragma unroll
        for (int p = 0; p < 2; p++) {
            double prod = acc[7 + 2 * p];
            double ssum = acc[8 + 2 * p];
            ssum = ssum > 1e-5 ? ssum : 1e-5;
            tv_sum += -prod / ssum;
        }

        out[0] = (float)(reg + LAMBDA * lcc_sum + BETA * tv_sum);

        // reset state for next graph replay
        #pragma unroll
        for (int i = 0; i < 12; i++) g_acc[i] = 0.0;
        __threadfence();
        g_count = 0u;
    }
}

extern "C" void kernel_launch(void* const* d_in, const int* in_sizes, int n_in,
                              void* d_out, int out_size) {
    const float* F0  = (const float*)d_in[0];
    const float* F0g = (const float*)d_in[1];
    const float* I0  = (const float*)d_in[2];
    const float* I0R = (const float*)d_in[3];
    const float* I1  = (const float*)d_in[4];
    const float* I1R = (const float*)d_in[5];
    const float* S0  = (const float*)d_in[6];
    const float* S0g = (const float*)d_in[7];
    const float* S1  = (const float*)d_in[8];
    const float* S1g = (const float*)d_in[9];
    float* out = (float*)d_out;

    main_kernel<<<NBLK, NT>>>(F0, F0g, I0, I0R, I1, I1R, S0, S0g, S1, S1g, out);
}